// round 11
// baseline (speedup 1.0000x reference)
#include <cuda_runtime.h>
#include <cuda_fp16.h>
#include <math.h>
#include <cstdint>

#define D_  1024
#define S_  2048
#define H_  16
#define HD_ 64
#define B_  2
#define M_  (B_ * S_)   // 4096

// Scratch (half precision activations/weights)
__device__ __half g_xh[M_ * D_];          // x in fp16
__device__ __half g_q[B_ * H_ * S_ * HD_]; // [B,H,S,HD], pre-scaled by 0.125*log2e
__device__ __half g_k[B_ * H_ * S_ * HD_]; // [B,H,S,HD]
__device__ __half g_v[B_ * H_ * HD_ * S_]; // [B,H,HD,S]  (transposed)
__device__ __half g_ctx[M_ * D_];          // [B,S,D]
__device__ __half g_wt[4][D_ * D_];        // transposed weights [N,K]: q,k,v,o

// ---------------------------------------------------------------------------
// helpers
// ---------------------------------------------------------------------------
__device__ __forceinline__ uint32_t smem_u32(const void* p) {
    uint32_t a;
    asm("{ .reg .u64 t; cvta.to.shared.u64 t, %1; cvt.u32.u64 %0, t; }"
        : "=r"(a) : "l"(p));
    return a;
}
__device__ __forceinline__ uint32_t h2_as_u32(__half2 h) {
    return *reinterpret_cast<uint32_t*>(&h);
}
__device__ __forceinline__ void cp_async16(uint32_t dst, const void* src) {
    asm volatile("cp.async.cg.shared.global [%0], [%1], 16;"
                 :: "r"(dst), "l"(src) : "memory");
}
#define CP_COMMIT() asm volatile("cp.async.commit_group;" ::: "memory")
#define CP_WAIT(n)  asm volatile("cp.async.wait_group %0;" :: "n"(n) : "memory")

// m16n8k16 fp16 MMA, fp32 accumulate
__device__ __forceinline__ void mma_f16(float* c, const uint32_t* a, const uint32_t* b) {
    asm volatile(
        "mma.sync.aligned.m16n8k16.row.col.f32.f16.f16.f32 "
        "{%0,%1,%2,%3}, {%4,%5,%6,%7}, {%8,%9}, {%0,%1,%2,%3};"
        : "+f"(c[0]), "+f"(c[1]), "+f"(c[2]), "+f"(c[3])
        : "r"(a[0]), "r"(a[1]), "r"(a[2]), "r"(a[3]), "r"(b[0]), "r"(b[1]));
}
__device__ __forceinline__ void ldsm_x4(uint32_t& r0, uint32_t& r1,
                                        uint32_t& r2, uint32_t& r3, uint32_t addr) {
    asm volatile("ldmatrix.sync.aligned.m8n8.x4.shared.b16 {%0,%1,%2,%3}, [%4];"
                 : "=r"(r0), "=r"(r1), "=r"(r2), "=r"(r3) : "r"(addr));
}
__device__ __forceinline__ void ldsm_x2(uint32_t& r0, uint32_t& r1, uint32_t addr) {
    asm volatile("ldmatrix.sync.aligned.m8n8.x2.shared.b16 {%0,%1}, [%2];"
                 : "=r"(r0), "=r"(r1) : "r"(addr));
}

// ---------------------------------------------------------------------------
// x: fp32 -> fp16
// ---------------------------------------------------------------------------
__global__ void f32_to_f16(const float4* __restrict__ in, __half2* __restrict__ out, int n4) {
    int i = blockIdx.x * blockDim.x + threadIdx.x;
    if (i < n4) {
        float4 v = in[i];
        out[2 * i]     = __floats2half2_rn(v.x, v.y);
        out[2 * i + 1] = __floats2half2_rn(v.z, v.w);
    }
}

// ---------------------------------------------------------------------------
// batched transpose + fp16: Wt[z][n][k] = half(W[z][k][n]), z in {0..3}
// ---------------------------------------------------------------------------
__global__ void transpose_w(const float* __restrict__ W0, const float* __restrict__ W1,
                            const float* __restrict__ W2, const float* __restrict__ W3,
                            __half* __restrict__ Wt) {
    __shared__ float tile[32][33];
    const float* W = (blockIdx.z == 0) ? W0 : (blockIdx.z == 1) ? W1
                     : (blockIdx.z == 2) ? W2 : W3;
    __half* dst = Wt + (size_t)blockIdx.z * D_ * D_;
    int x = blockIdx.x * 32 + threadIdx.x;
    int y = blockIdx.y * 32 + threadIdx.y;
#pragma unroll
    for (int j = 0; j < 32; j += 8)
        tile[threadIdx.y + j][threadIdx.x] = W[(size_t)(y + j) * D_ + x];
    __syncthreads();
    x = blockIdx.y * 32 + threadIdx.x;
    y = blockIdx.x * 32 + threadIdx.y;
#pragma unroll
    for (int j = 0; j < 32; j += 8)
        dst[(size_t)(y + j) * D_ + x] = __float2half(tile[threadIdx.x][threadIdx.y + j]);
}

// ---------------------------------------------------------------------------
// fp16 mma GEMM. CTA 128x128, 4 warps, K-stage 64, cp.async double buffer.
// Fragment loads via ldmatrix.
// MODE 0: fp32 row-major out (final projection), bias = b0, out = C0
// MODE 3: fused QKV — Wt is [3072,1024]; epilogue dispatches per 1024-col
//         segment: seg0 -> Q (C0, bias b0, * 0.125*log2e), seg1 -> K (C1, b1),
//         seg2 -> V (C2, b2, transposed [B,H,HD,S])
// ---------------------------------------------------------------------------
#define KS 64
#define NSTAGE (D_ / KS)          // 16
#define PADH 72                   // padded k-stride in halves (144B = 9*16B)
#define STAGE_H (128 * PADH)      // halves per buffer

#define QSCALE 0.18033688011112042f   // 0.125 * log2(e)

template <int MODE>
__global__ __launch_bounds__(128) void gemm_f16(const __half* __restrict__ A,
                                                const __half* __restrict__ Wt,
                                                const float* __restrict__ b0,
                                                const float* __restrict__ b1,
                                                const float* __restrict__ b2,
                                                void* __restrict__ C0,
                                                void* __restrict__ C1,
                                                void* __restrict__ C2) {
    extern __shared__ __half smh[];
    const int tid  = threadIdx.x;
    const int wid  = tid >> 5;
    const int lane = tid & 31;
    const int g = lane >> 2;
    const int t = lane & 3;
    const int warp_m = (wid & 1) * 64;
    const int warp_n = (wid >> 1) * 64;
    const int row0 = blockIdx.y * 128;
    const int col0 = blockIdx.x * 128;

    const uint32_t s_u = smem_u32(smh);

    // ldmatrix lane-address components
    const int mrow = lane & 7;
    const int msel = lane >> 3;            // matrix index 0..3
    const int a_roff = (msel & 1) * 8;     // A: m1,m3 are rows+8
    const int a_koff = (msel & 2) ? 8 : 0; // A: m2,m3 are k+8
    const int b_noff = (msel & 2) ? 8 : 0; // B: m2,m3 are n+8
    const int b_koff = (msel & 1) ? 8 : 0; // B: m1,m3 are k+8

    float acc[4][8][4];
#pragma unroll
    for (int mt = 0; mt < 4; mt++)
#pragma unroll
        for (int nt = 0; nt < 8; nt++)
#pragma unroll
            for (int r = 0; r < 4; r++) acc[mt][nt][r] = 0.0f;

    auto issue_stage = [&](int s) {
        const int k0 = s * KS;
        const int buf = s & 1;
        const uint32_t baseA = s_u + (uint32_t)buf * STAGE_H * 2u;
        const uint32_t baseB = s_u + (uint32_t)(2 + buf) * STAGE_H * 2u;
#pragma unroll
        for (int i = 0; i < 8; i++) {
            const int lin = tid + i * 128;
            const int row = lin >> 3;
            const int f8  = (lin & 7) * 8;
            cp_async16(baseA + (uint32_t)(row * PADH + f8) * 2u,
                       &A[(size_t)(row0 + row) * D_ + k0 + f8]);
            cp_async16(baseB + (uint32_t)(row * PADH + f8) * 2u,
                       &Wt[(size_t)(col0 + row) * D_ + k0 + f8]);
        }
        CP_COMMIT();
    };

    issue_stage(0);
    issue_stage(1);

    for (int s = 0; s < NSTAGE; s++) {
        if (s + 1 < NSTAGE) { CP_WAIT(1); } else { CP_WAIT(0); }
        __syncthreads();

        const int buf = s & 1;
        const uint32_t pA_u = s_u + (uint32_t)buf * STAGE_H * 2u;
        const uint32_t pB_u = s_u + (uint32_t)(2 + buf) * STAGE_H * 2u;

#pragma unroll
        for (int k16 = 0; k16 < 4; k16++) {
            const int kkb = k16 * 16;
            uint32_t af[4][4], bf[8][2];
#pragma unroll
            for (int mt = 0; mt < 4; mt++) {
                ldsm_x4(af[mt][0], af[mt][1], af[mt][2], af[mt][3],
                        pA_u + (uint32_t)((warp_m + mt * 16 + a_roff + mrow) * PADH
                                          + kkb + a_koff) * 2u);
            }
#pragma unroll
            for (int np = 0; np < 4; np++) {
                ldsm_x4(bf[2 * np][0], bf[2 * np][1], bf[2 * np + 1][0], bf[2 * np + 1][1],
                        pB_u + (uint32_t)((warp_n + np * 16 + b_noff + mrow) * PADH
                                          + kkb + b_koff) * 2u);
            }
#pragma unroll
            for (int mt = 0; mt < 4; mt++)
#pragma unroll
                for (int nt = 0; nt < 8; nt++)
                    mma_f16(acc[mt][nt], af[mt], bf[nt]);
        }
        __syncthreads();
        if (s + 2 < NSTAGE) issue_stage(s + 2);
    }

    // epilogue
#pragma unroll
    for (int mt = 0; mt < 4; mt++) {
        const int r_lo = row0 + warp_m + mt * 16 + g;
#pragma unroll
        for (int nt = 0; nt < 8; nt++) {
            const int cc = col0 + warp_n + nt * 8 + 2 * t;
            const int seg = cc >> 10;          // 0=Q 1=K 2=V (MODE 3; CTA-uniform)
            const int lc  = cc & (D_ - 1);
            const float* bias = (MODE == 0) ? b0
                               : (seg == 0) ? b0 : (seg == 1) ? b1 : b2;
            const int bidx = (MODE == 0) ? cc : lc;
            const float bx = bias[bidx];
            const float by = bias[bidx + 1];
#pragma unroll
            for (int half_ = 0; half_ < 2; half_++) {
                const int rr = r_lo + half_ * 8;
                const float v0 = acc[mt][nt][2 * half_ + 0] + bx;
                const float v1 = acc[mt][nt][2 * half_ + 1] + by;
                if (MODE == 0) {
                    float* C = (float*)C0;
                    *reinterpret_cast<float2*>(&C[(size_t)rr * D_ + cc]) =
                        make_float2(v0, v1);
                } else {
                    const int bb = rr >> 11;
                    const int ss = rr & (S_ - 1);
                    const int hh = lc >> 6;
                    const int dd = lc & (HD_ - 1);
                    if (seg == 0) {
                        __half* C = (__half*)C0;
                        *reinterpret_cast<__half2*>(
                            &C[(((size_t)(bb * H_ + hh)) * S_ + ss) * HD_ + dd]) =
                            __floats2half2_rn(v0 * QSCALE, v1 * QSCALE);
                    } else if (seg == 1) {
                        __half* C = (__half*)C1;
                        *reinterpret_cast<__half2*>(
                            &C[(((size_t)(bb * H_ + hh)) * S_ + ss) * HD_ + dd]) =
                            __floats2half2_rn(v0, v1);
                    } else {
                        __half* C = (__half*)C2;
                        C[(((size_t)(bb * H_ + hh)) * HD_ + dd) * S_ + ss] = __float2half(v0);
                        C[(((size_t)(bb * H_ + hh)) * HD_ + dd + 1) * S_ + ss] = __float2half(v1);
                    }
                }
            }
        }
    }
}

// ---------------------------------------------------------------------------
// fp16 tensor-core flash attention, 128-query tile, log2-domain softmax,
// cross-iteration software pipeline: softmax(i) uses scores computed in
// iteration i-1, so it never waits on fresh mma results.
// 3-stage smem ring (prefetch depth 2), ONE __syncthreads per iteration.
// CTA = (128-q tile, h, b); 8 warps; warp w owns q rows [16w, 16w+16).
// Q pre-scaled by 0.125*log2e. V is [B,H,HD,S]. P in registers (h2exp2).
// V smem tile has 8 extra rows: row 64 = ones -> l accumulates in the PV mma.
// ---------------------------------------------------------------------------
#define PADA 72
#define TILE_HK (64 * PADA)   // halves per K tile
#define TILE_HV (72 * PADA)   // halves per V tile (64 data rows + 8 ones/zeros)
#define NTILE (S_ / 64)       // 32

__global__ __launch_bounds__(256) void attn_f16(const __half* __restrict__ Q,
                                                const __half* __restrict__ K,
                                                const __half* __restrict__ V,
                                                __half* __restrict__ ctx) {
    extern __shared__ __half sah[];
    // layout: K stages 0..2 (TILE_HK each) | V stages 0..2 (TILE_HV each)
    const int tid  = threadIdx.x;
    const int wid  = tid >> 5;        // 0..7
    const int lane = tid & 31;
    const int g = lane >> 2;
    const int t = lane & 3;
    const int qt = blockIdx.x;
    const int h  = blockIdx.y;
    const int b  = blockIdx.z;
    const size_t bh = ((size_t)b * H_ + h);
    const int q0 = qt * 128;

    __half* sK  = sah;
    __half* sVt = sah + 3 * TILE_HK;
    const uint32_t sK_u  = smem_u32(sK);
    const uint32_t sVt_u = smem_u32(sVt);

    // ldmatrix lane-address components (B-operand pattern)
    const int mrow = lane & 7;
    const int msel = lane >> 3;
    const int b_noff = (msel & 2) ? 8 : 0;
    const int b_koff = (msel & 1) ? 8 : 0;
    const int x2_koff = (lane & 8) ? 8 : 0;   // for ldsm_x2 (lanes 0-15)

    // init V rows 64..71 of all 3 stages: row 64 = 1.0, rows 65..71 = 0.0
    for (int idx = tid; idx < 3 * 8 * PADA; idx += 256) {
        const int buf = idx / (8 * PADA);
        const int rem = idx % (8 * PADA);
        const int r = 64 + rem / PADA;
        const int c = rem % PADA;
        sVt[buf * TILE_HV + r * PADA + c] = __float2half(r == 64 ? 1.0f : 0.0f);
    }

    // Q fragments in registers (4 k16-steps over HD=64)
    const __half* Qp = Q + (bh * S_ + q0 + wid * 16) * HD_;
    uint32_t qf[4][4];
#pragma unroll
    for (int kt = 0; kt < 4; kt++) {
        const int kk = kt * 16 + 2 * t;
        qf[kt][0] = *reinterpret_cast<const uint32_t*>(&Qp[g * HD_ + kk]);
        qf[kt][1] = *reinterpret_cast<const uint32_t*>(&Qp[(g + 8) * HD_ + kk]);
        qf[kt][2] = *reinterpret_cast<const uint32_t*>(&Qp[g * HD_ + kk + 8]);
        qf[kt][3] = *reinterpret_cast<const uint32_t*>(&Qp[(g + 8) * HD_ + kk + 8]);
    }

    float o[9][4];   // o[8] = l (via ones row in V)
#pragma unroll
    for (int nt = 0; nt < 9; nt++)
#pragma unroll
        for (int r = 0; r < 4; r++) o[nt][r] = 0.0f;
    float m0 = -INFINITY, m1 = -INFINITY;

    const __half* Kbase = K + bh * S_ * HD_;
    const __half* Vbase = V + bh * (size_t)HD_ * S_;

    auto load_tile = [&](int i, int buf) {
        const __half* Kp = Kbase + (size_t)i * 64 * HD_;
        const uint32_t dK = sK_u + (uint32_t)buf * TILE_HK * 2u;
        const uint32_t dV = sVt_u + (uint32_t)buf * TILE_HV * 2u;
#pragma unroll
        for (int j = 0; j < 2; j++) {
            const int lin = tid + j * 256;   // 0..511
            const int row = lin >> 3;        // 0..63
            const int f8  = (lin & 7) * 8;   // halves
            cp_async16(dK + (uint32_t)(row * PADA + f8) * 2u, Kp + row * HD_ + f8);
            cp_async16(dV + (uint32_t)(row * PADA + f8) * 2u,
                       Vbase + (size_t)row * S_ + i * 64 + f8);
        }
        CP_COMMIT();
    };

    float s[8][4];   // scores for the CURRENT softmax tile (computed 1 iter ago)

    auto qk_tile = [&](int stage) {
        const uint32_t cK_u = sK_u + (uint32_t)stage * TILE_HK * 2u;
#pragma unroll
        for (int nt = 0; nt < 8; nt++)
#pragma unroll
            for (int r = 0; r < 4; r++) s[nt][r] = 0.0f;
#pragma unroll
        for (int kt = 0; kt < 4; kt++) {
            const int kkb = kt * 16;
#pragma unroll
            for (int np = 0; np < 4; np++) {
                uint32_t bf0[2], bf1[2];
                ldsm_x4(bf0[0], bf0[1], bf1[0], bf1[1],
                        cK_u + (uint32_t)((np * 16 + b_noff + mrow) * PADA
                                          + kkb + b_koff) * 2u);
                mma_f16(s[2 * np],     qf[kt], bf0);
                mma_f16(s[2 * np + 1], qf[kt], bf1);
            }
        }
    };

    // prologue: stage loads for tiles 0,1; compute s(0)
    load_tile(0, 0);
    load_tile(1, 1);
    CP_WAIT(1);          // tile 0 complete
    __syncthreads();
    qk_tile(0);

    for (int i = 0; i < NTILE; i++) {
        CP_WAIT(0);      // tile i+1 complete (the only pending group)
        __syncthreads(); // visibility + all warps done with stage (i-1)%3
        if (i + 2 < NTILE) load_tile(i + 2, (i + 2) % 3);

        // ---- softmax on s (tile i) -> pa; s dies here ----
        float mx0 = -INFINITY, mx1 = -INFINITY;
#pragma unroll
        for (int nt = 0; nt < 8; nt++) {
            mx0 = fmaxf(mx0, fmaxf(s[nt][0], s[nt][1]));
            mx1 = fmaxf(mx1, fmaxf(s[nt][2], s[nt][3]));
        }
        mx0 = fmaxf(mx0, __shfl_xor_sync(0xffffffffu, mx0, 1));
        mx0 = fmaxf(mx0, __shfl_xor_sync(0xffffffffu, mx0, 2));
        mx1 = fmaxf(mx1, __shfl_xor_sync(0xffffffffu, mx1, 1));
        mx1 = fmaxf(mx1, __shfl_xor_sync(0xffffffffu, mx1, 2));

        // warp-uniform skip of rescale when the running max is unchanged
        if (__any_sync(0xffffffffu, (mx0 > m0) || (mx1 > m1))) {
            const float mn0 = fmaxf(m0, mx0);
            const float mn1 = fmaxf(m1, mx1);
            const float f0 = exp2f(m0 - mn0);
            const float f1 = exp2f(m1 - mn1);
            m0 = mn0; m1 = mn1;
#pragma unroll
            for (int nt = 0; nt < 9; nt++) {
                o[nt][0] *= f0; o[nt][1] *= f0;
                o[nt][2] *= f1; o[nt][3] *= f1;
            }
        }

        uint32_t pa[4][4];
#pragma unroll
        for (int kt = 0; kt < 4; kt++) {
            pa[kt][0] = h2_as_u32(h2exp2(__floats2half2_rn(s[2 * kt][0] - m0,
                                                           s[2 * kt][1] - m0)));
            pa[kt][1] = h2_as_u32(h2exp2(__floats2half2_rn(s[2 * kt][2] - m1,
                                                           s[2 * kt][3] - m1)));
            pa[kt][2] = h2_as_u32(h2exp2(__floats2half2_rn(s[2 * kt + 1][0] - m0,
                                                           s[2 * kt + 1][1] - m0)));
            pa[kt][3] = h2_as_u32(h2exp2(__floats2half2_rn(s[2 * kt + 1][2] - m1,
                                                           s[2 * kt + 1][3] - m1)));
        }

        // ---- PV(i): 9 n-groups (group 8 = ones row -> l) ----
        const uint32_t cV_u = sVt_u + (uint32_t)(i % 3) * TILE_HV * 2u;
#pragma unroll
        for (int kt = 0; kt < 4; kt++) {
            const int kkb = kt * 16;
#pragma unroll
            for (int np = 0; np < 4; np++) {
                uint32_t bf0[2], bf1[2];
                ldsm_x4(bf0[0], bf0[1], bf1[0], bf1[1],
                        cV_u + (uint32_t)((np * 16 + b_noff + mrow) * PADA
                                          + kkb + b_koff) * 2u);
                mma_f16(o[2 * np],     pa[kt], bf0);
                mma_f16(o[2 * np + 1], pa[kt], bf1);
            }
            {
                uint32_t bf[2];
                ldsm_x2(bf[0], bf[1],
                        cV_u + (uint32_t)((64 + mrow) * PADA + kkb + x2_koff) * 2u);
                mma_f16(o[8], pa[kt], bf);
            }
        }

        // ---- QK(i+1) into s (independent of this iteration's softmax) ----
        if (i + 1 < NTILE) qk_tile((i + 1) % 3);
    }

    // recover l from the quad leader (t=0 holds column 64)
    const float l0 = __shfl_sync(0xffffffffu, o[8][0], lane & 28);
    const float l1 = __shfl_sync(0xffffffffu, o[8][2], lane & 28);
    const float inv0 = 1.0f / l0;
    const float inv1 = 1.0f / l1;

    // epilogue: ctx half [B,S,D]
    const size_t row_lo = (size_t)b * S_ + q0 + wid * 16 + g;
#pragma unroll
    for (int nt = 0; nt < 8; nt++) {
        const int col = h * HD_ + nt * 8 + 2 * t;
        *reinterpret_cast<__half2*>(&ctx[row_lo * D_ + col]) =
            __floats2half2_rn(o[nt][0] * inv0, o[nt][1] * inv0);
        *reinterpret_cast<__half2*>(&ctx[(row_lo + 8) * D_ + col]) =
            __floats2half2_rn(o[nt][2] * inv1, o[nt][3] * inv1);
    }
}

// ---------------------------------------------------------------------------
extern "C" void kernel_launch(void* const* d_in, const int* in_sizes, int n_in,
                              void* d_out, int out_size) {
    const float* x  = (const float*)d_in[0];
    const float* Wq = (const float*)d_in[1];
    const float* bq = (const float*)d_in[2];
    const float* Wk = (const float*)d_in[3];
    const float* bk = (const float*)d_in[4];
    const float* Wv = (const float*)d_in[5];
    const float* bv = (const float*)d_in[6];
    const float* Wo = (const float*)d_in[7];
    const float* bo = (const float*)d_in[8];
    float* out = (float*)d_out;

    __half *xh, *q, *k, *v, *ctx, *wt;
    cudaGetSymbolAddress((void**)&xh,  g_xh);
    cudaGetSymbolAddress((void**)&q,   g_q);
    cudaGetSymbolAddress((void**)&k,   g_k);
    cudaGetSymbolAddress((void**)&v,   g_v);
    cudaGetSymbolAddress((void**)&ctx, g_ctx);
    cudaGetSymbolAddress((void**)&wt,  g_wt);
    __half* wto = wt + 3 * D_ * D_;

    const int gemm_smem = 4 * STAGE_H * 2;                  // 73728 B
    const int attn_smem = (3 * TILE_HK + 3 * TILE_HV) * 2;  // 58752 B
    cudaFuncSetAttribute(gemm_f16<0>, cudaFuncAttributeMaxDynamicSharedMemorySize, gemm_smem);
    cudaFuncSetAttribute(gemm_f16<3>, cudaFuncAttributeMaxDynamicSharedMemorySize, gemm_smem);
    cudaFuncSetAttribute(attn_f16, cudaFuncAttributeMaxDynamicSharedMemorySize, attn_smem);

    const int n4 = M_ * D_ / 4;
    f32_to_f16<<<(n4 + 255) / 256, 256>>>((const float4*)x, (__half2*)xh, n4);

    dim3 tr_grid(32, 32, 4), tr_blk(32, 8);
    transpose_w<<<tr_grid, tr_blk>>>(Wq, Wk, Wv, Wo, wt);

    // fused QKV GEMM: N = 3072
    dim3 gqkv(3 * D_ / 128, M_ / 128);   // (24, 32)
    gemm_f16<3><<<gqkv, 128, gemm_smem>>>(xh, wt, bq, bk, bv, q, k, v);

    dim3 attn_grid(S_ / 128, H_, B_);    // (16, 16, 2)
    attn_f16<<<attn_grid, 256, attn_smem>>>(q, k, v, ctx);

    dim3 gg(D_ / 128, M_ / 128);         // (8, 32)
    gemm_f16<0><<<gg, 128, gemm_smem>>>(ctx, wto, bo, nullptr, nullptr, out, nullptr, nullptr);
}

// round 12
// speedup vs baseline: 1.0637x; 1.0637x over previous
#include <cuda_runtime.h>
#include <cuda_fp16.h>
#include <math.h>
#include <cstdint>

#define D_  1024
#define S_  2048
#define H_  16
#define HD_ 64
#define B_  2
#define M_  (B_ * S_)   // 4096

// Scratch (half precision activations/weights)
__device__ __half g_xh[M_ * D_];          // x in fp16
__device__ __half g_q[B_ * H_ * S_ * HD_]; // [B,H,S,HD], pre-scaled by 0.125*log2e
__device__ __half g_k[B_ * H_ * S_ * HD_]; // [B,H,S,HD]
__device__ __half g_v[B_ * H_ * HD_ * S_]; // [B,H,HD,S]  (transposed)
__device__ __half g_ctx[M_ * D_];          // [B,S,D]
__device__ __half g_wt[4][D_ * D_];        // transposed weights [N,K]: q,k,v,o

// ---------------------------------------------------------------------------
// helpers
// ---------------------------------------------------------------------------
__device__ __forceinline__ uint32_t smem_u32(const void* p) {
    uint32_t a;
    asm("{ .reg .u64 t; cvta.to.shared.u64 t, %1; cvt.u32.u64 %0, t; }"
        : "=r"(a) : "l"(p));
    return a;
}
__device__ __forceinline__ uint32_t h2_as_u32(__half2 h) {
    return *reinterpret_cast<uint32_t*>(&h);
}
__device__ __forceinline__ void cp_async16(uint32_t dst, const void* src) {
    asm volatile("cp.async.cg.shared.global [%0], [%1], 16;"
                 :: "r"(dst), "l"(src) : "memory");
}
#define CP_COMMIT() asm volatile("cp.async.commit_group;" ::: "memory")
#define CP_WAIT(n)  asm volatile("cp.async.wait_group %0;" :: "n"(n) : "memory")

// m16n8k16 fp16 MMA, fp32 accumulate
__device__ __forceinline__ void mma_f16(float* c, const uint32_t* a, const uint32_t* b) {
    asm volatile(
        "mma.sync.aligned.m16n8k16.row.col.f32.f16.f16.f32 "
        "{%0,%1,%2,%3}, {%4,%5,%6,%7}, {%8,%9}, {%0,%1,%2,%3};"
        : "+f"(c[0]), "+f"(c[1]), "+f"(c[2]), "+f"(c[3])
        : "r"(a[0]), "r"(a[1]), "r"(a[2]), "r"(a[3]), "r"(b[0]), "r"(b[1]));
}
__device__ __forceinline__ void ldsm_x4(uint32_t& r0, uint32_t& r1,
                                        uint32_t& r2, uint32_t& r3, uint32_t addr) {
    asm volatile("ldmatrix.sync.aligned.m8n8.x4.shared.b16 {%0,%1,%2,%3}, [%4];"
                 : "=r"(r0), "=r"(r1), "=r"(r2), "=r"(r3) : "r"(addr));
}
__device__ __forceinline__ void ldsm_x2(uint32_t& r0, uint32_t& r1, uint32_t addr) {
    asm volatile("ldmatrix.sync.aligned.m8n8.x2.shared.b16 {%0,%1}, [%2];"
                 : "=r"(r0), "=r"(r1) : "r"(addr));
}

// ---------------------------------------------------------------------------
// x: fp32 -> fp16
// ---------------------------------------------------------------------------
__global__ void f32_to_f16(const float4* __restrict__ in, __half2* __restrict__ out, int n4) {
    int i = blockIdx.x * blockDim.x + threadIdx.x;
    if (i < n4) {
        float4 v = in[i];
        out[2 * i]     = __floats2half2_rn(v.x, v.y);
        out[2 * i + 1] = __floats2half2_rn(v.z, v.w);
    }
}

// ---------------------------------------------------------------------------
// batched transpose + fp16: Wt[z][n][k] = half(W[z][k][n]), z in {0..3}
// ---------------------------------------------------------------------------
__global__ void transpose_w(const float* __restrict__ W0, const float* __restrict__ W1,
                            const float* __restrict__ W2, const float* __restrict__ W3,
                            __half* __restrict__ Wt) {
    __shared__ float tile[32][33];
    const float* W = (blockIdx.z == 0) ? W0 : (blockIdx.z == 1) ? W1
                     : (blockIdx.z == 2) ? W2 : W3;
    __half* dst = Wt + (size_t)blockIdx.z * D_ * D_;
    int x = blockIdx.x * 32 + threadIdx.x;
    int y = blockIdx.y * 32 + threadIdx.y;
#pragma unroll
    for (int j = 0; j < 32; j += 8)
        tile[threadIdx.y + j][threadIdx.x] = W[(size_t)(y + j) * D_ + x];
    __syncthreads();
    x = blockIdx.y * 32 + threadIdx.x;
    y = blockIdx.x * 32 + threadIdx.y;
#pragma unroll
    for (int j = 0; j < 32; j += 8)
        dst[(size_t)(y + j) * D_ + x] = __float2half(tile[threadIdx.x][threadIdx.y + j]);
}

// ---------------------------------------------------------------------------
// fp16 mma GEMM. CTA 128x128, 4 warps, K-stage 64, cp.async double buffer.
// Fragment loads via ldmatrix.
// MODE 0: fp32 row-major out (final projection), bias = b0, out = C0
// MODE 3: fused QKV — Wt is [3072,1024]; epilogue dispatches per 1024-col
//         segment: seg0 -> Q (C0, bias b0, * 0.125*log2e), seg1 -> K (C1, b1),
//         seg2 -> V (C2, b2, transposed [B,H,HD,S])
// ---------------------------------------------------------------------------
#define KS 64
#define NSTAGE (D_ / KS)          // 16
#define PADH 72                   // padded k-stride in halves (144B = 9*16B)
#define STAGE_H (128 * PADH)      // halves per buffer

#define QSCALE 0.18033688011112042f   // 0.125 * log2(e)

template <int MODE>
__global__ __launch_bounds__(128) void gemm_f16(const __half* __restrict__ A,
                                                const __half* __restrict__ Wt,
                                                const float* __restrict__ b0,
                                                const float* __restrict__ b1,
                                                const float* __restrict__ b2,
                                                void* __restrict__ C0,
                                                void* __restrict__ C1,
                                                void* __restrict__ C2) {
    extern __shared__ __half smh[];
    const int tid  = threadIdx.x;
    const int wid  = tid >> 5;
    const int lane = tid & 31;
    const int g = lane >> 2;
    const int t = lane & 3;
    const int warp_m = (wid & 1) * 64;
    const int warp_n = (wid >> 1) * 64;
    const int row0 = blockIdx.y * 128;
    const int col0 = blockIdx.x * 128;

    const uint32_t s_u = smem_u32(smh);

    // ldmatrix lane-address components
    const int mrow = lane & 7;
    const int msel = lane >> 3;            // matrix index 0..3
    const int a_roff = (msel & 1) * 8;     // A: m1,m3 are rows+8
    const int a_koff = (msel & 2) ? 8 : 0; // A: m2,m3 are k+8
    const int b_noff = (msel & 2) ? 8 : 0; // B: m2,m3 are n+8
    const int b_koff = (msel & 1) ? 8 : 0; // B: m1,m3 are k+8

    float acc[4][8][4];
#pragma unroll
    for (int mt = 0; mt < 4; mt++)
#pragma unroll
        for (int nt = 0; nt < 8; nt++)
#pragma unroll
            for (int r = 0; r < 4; r++) acc[mt][nt][r] = 0.0f;

    auto issue_stage = [&](int s) {
        const int k0 = s * KS;
        const int buf = s & 1;
        const uint32_t baseA = s_u + (uint32_t)buf * STAGE_H * 2u;
        const uint32_t baseB = s_u + (uint32_t)(2 + buf) * STAGE_H * 2u;
#pragma unroll
        for (int i = 0; i < 8; i++) {
            const int lin = tid + i * 128;
            const int row = lin >> 3;
            const int f8  = (lin & 7) * 8;
            cp_async16(baseA + (uint32_t)(row * PADH + f8) * 2u,
                       &A[(size_t)(row0 + row) * D_ + k0 + f8]);
            cp_async16(baseB + (uint32_t)(row * PADH + f8) * 2u,
                       &Wt[(size_t)(col0 + row) * D_ + k0 + f8]);
        }
        CP_COMMIT();
    };

    issue_stage(0);
    issue_stage(1);

    for (int s = 0; s < NSTAGE; s++) {
        if (s + 1 < NSTAGE) { CP_WAIT(1); } else { CP_WAIT(0); }
        __syncthreads();

        const int buf = s & 1;
        const uint32_t pA_u = s_u + (uint32_t)buf * STAGE_H * 2u;
        const uint32_t pB_u = s_u + (uint32_t)(2 + buf) * STAGE_H * 2u;

#pragma unroll
        for (int k16 = 0; k16 < 4; k16++) {
            const int kkb = k16 * 16;
            uint32_t af[4][4], bf[8][2];
#pragma unroll
            for (int mt = 0; mt < 4; mt++) {
                ldsm_x4(af[mt][0], af[mt][1], af[mt][2], af[mt][3],
                        pA_u + (uint32_t)((warp_m + mt * 16 + a_roff + mrow) * PADH
                                          + kkb + a_koff) * 2u);
            }
#pragma unroll
            for (int np = 0; np < 4; np++) {
                ldsm_x4(bf[2 * np][0], bf[2 * np][1], bf[2 * np + 1][0], bf[2 * np + 1][1],
                        pB_u + (uint32_t)((warp_n + np * 16 + b_noff + mrow) * PADH
                                          + kkb + b_koff) * 2u);
            }
#pragma unroll
            for (int mt = 0; mt < 4; mt++)
#pragma unroll
                for (int nt = 0; nt < 8; nt++)
                    mma_f16(acc[mt][nt], af[mt], bf[nt]);
        }
        __syncthreads();
        if (s + 2 < NSTAGE) issue_stage(s + 2);
    }

    // epilogue
#pragma unroll
    for (int mt = 0; mt < 4; mt++) {
        const int r_lo = row0 + warp_m + mt * 16 + g;
#pragma unroll
        for (int nt = 0; nt < 8; nt++) {
            const int cc = col0 + warp_n + nt * 8 + 2 * t;
            const int seg = cc >> 10;          // 0=Q 1=K 2=V (MODE 3; CTA-uniform)
            const int lc  = cc & (D_ - 1);
            const float* bias = (MODE == 0) ? b0
                               : (seg == 0) ? b0 : (seg == 1) ? b1 : b2;
            const int bidx = (MODE == 0) ? cc : lc;
            const float bx = bias[bidx];
            const float by = bias[bidx + 1];
#pragma unroll
            for (int half_ = 0; half_ < 2; half_++) {
                const int rr = r_lo + half_ * 8;
                const float v0 = acc[mt][nt][2 * half_ + 0] + bx;
                const float v1 = acc[mt][nt][2 * half_ + 1] + by;
                if (MODE == 0) {
                    float* C = (float*)C0;
                    *reinterpret_cast<float2*>(&C[(size_t)rr * D_ + cc]) =
                        make_float2(v0, v1);
                } else {
                    const int bb = rr >> 11;
                    const int ss = rr & (S_ - 1);
                    const int hh = lc >> 6;
                    const int dd = lc & (HD_ - 1);
                    if (seg == 0) {
                        __half* C = (__half*)C0;
                        *reinterpret_cast<__half2*>(
                            &C[(((size_t)(bb * H_ + hh)) * S_ + ss) * HD_ + dd]) =
                            __floats2half2_rn(v0 * QSCALE, v1 * QSCALE);
                    } else if (seg == 1) {
                        __half* C = (__half*)C1;
                        *reinterpret_cast<__half2*>(
                            &C[(((size_t)(bb * H_ + hh)) * S_ + ss) * HD_ + dd]) =
                            __floats2half2_rn(v0, v1);
                    } else {
                        __half* C = (__half*)C2;
                        C[(((size_t)(bb * H_ + hh)) * HD_ + dd) * S_ + ss] = __float2half(v0);
                        C[(((size_t)(bb * H_ + hh)) * HD_ + dd + 1) * S_ + ss] = __float2half(v1);
                    }
                }
            }
        }
    }
}

// ---------------------------------------------------------------------------
// fp16 tensor-core flash attention, 64-query tile, 4 warps, 4 CTAs/SM.
// log2-domain softmax, cross-iteration software pipeline (softmax(i) uses
// scores computed in iteration i-1). K ring 2-stage, V ring 3-stage,
// ONE __syncthreads per iteration.
// CTA = (64-q tile, h, b); warp w owns q rows [16w, 16w+16).
// Q pre-scaled by 0.125*log2e. V is [B,H,HD,S]. P in registers (h2exp2).
// V smem tile has 8 extra rows: row 64 = ones -> l accumulates in the PV mma.
// ---------------------------------------------------------------------------
#define PADA 72
#define TILE_HK (64 * PADA)   // halves per K tile
#define TILE_HV (72 * PADA)   // halves per V tile (64 data rows + 8 ones/zeros)
#define NTILE (S_ / 64)       // 32

__global__ __launch_bounds__(128, 4) void attn_f16(const __half* __restrict__ Q,
                                                   const __half* __restrict__ K,
                                                   const __half* __restrict__ V,
                                                   __half* __restrict__ ctx) {
    extern __shared__ __half sah[];
    // layout: K stages 0..1 (TILE_HK each) | V stages 0..2 (TILE_HV each)
    const int tid  = threadIdx.x;
    const int wid  = tid >> 5;        // 0..3
    const int lane = tid & 31;
    const int g = lane >> 2;
    const int t = lane & 3;
    const int qt = blockIdx.x;
    const int h  = blockIdx.y;
    const int b  = blockIdx.z;
    const size_t bh = ((size_t)b * H_ + h);
    const int q0 = qt * 64;

    __half* sK  = sah;
    __half* sVt = sah + 2 * TILE_HK;
    const uint32_t sK_u  = smem_u32(sK);
    const uint32_t sVt_u = smem_u32(sVt);

    // ldmatrix lane-address components (B-operand pattern)
    const int mrow = lane & 7;
    const int msel = lane >> 3;
    const int b_noff = (msel & 2) ? 8 : 0;
    const int b_koff = (msel & 1) ? 8 : 0;
    const int x2_koff = (lane & 8) ? 8 : 0;   // for ldsm_x2 (lanes 0-15)

    // init V rows 64..71 of all 3 stages: row 64 = 1.0, rows 65..71 = 0.0
    for (int idx = tid; idx < 3 * 8 * PADA; idx += 128) {
        const int buf = idx / (8 * PADA);
        const int rem = idx % (8 * PADA);
        const int r = 64 + rem / PADA;
        const int c = rem % PADA;
        sVt[buf * TILE_HV + r * PADA + c] = __float2half(r == 64 ? 1.0f : 0.0f);
    }

    // Q fragments in registers (4 k16-steps over HD=64)
    const __half* Qp = Q + (bh * S_ + q0 + wid * 16) * HD_;
    uint32_t qf[4][4];
#pragma unroll
    for (int kt = 0; kt < 4; kt++) {
        const int kk = kt * 16 + 2 * t;
        qf[kt][0] = *reinterpret_cast<const uint32_t*>(&Qp[g * HD_ + kk]);
        qf[kt][1] = *reinterpret_cast<const uint32_t*>(&Qp[(g + 8) * HD_ + kk]);
        qf[kt][2] = *reinterpret_cast<const uint32_t*>(&Qp[g * HD_ + kk + 8]);
        qf[kt][3] = *reinterpret_cast<const uint32_t*>(&Qp[(g + 8) * HD_ + kk + 8]);
    }

    float o[9][4];   // o[8] = l (via ones row in V)
#pragma unroll
    for (int nt = 0; nt < 9; nt++)
#pragma unroll
        for (int r = 0; r < 4; r++) o[nt][r] = 0.0f;
    float m0 = -INFINITY, m1 = -INFINITY;

    const __half* Kbase = K + bh * S_ * HD_;
    const __half* Vbase = V + bh * (size_t)HD_ * S_;

    // loads K(i) into K-stage i&1, V(i) into V-stage i%3
    auto load_tile = [&](int i) {
        const __half* Kp = Kbase + (size_t)i * 64 * HD_;
        const uint32_t dK = sK_u + (uint32_t)(i & 1) * TILE_HK * 2u;
        const uint32_t dV = sVt_u + (uint32_t)(i % 3) * TILE_HV * 2u;
#pragma unroll
        for (int j = 0; j < 4; j++) {
            const int lin = tid + j * 128;   // 0..511
            const int row = lin >> 3;        // 0..63
            const int f8  = (lin & 7) * 8;   // halves
            cp_async16(dK + (uint32_t)(row * PADA + f8) * 2u, Kp + row * HD_ + f8);
            cp_async16(dV + (uint32_t)(row * PADA + f8) * 2u,
                       Vbase + (size_t)row * S_ + i * 64 + f8);
        }
        CP_COMMIT();
    };

    float s[8][4];   // scores for the CURRENT softmax tile (computed 1 iter ago)

    auto qk_tile = [&](int stage) {
        const uint32_t cK_u = sK_u + (uint32_t)stage * TILE_HK * 2u;
#pragma unroll
        for (int nt = 0; nt < 8; nt++)
#pragma unroll
            for (int r = 0; r < 4; r++) s[nt][r] = 0.0f;
#pragma unroll
        for (int kt = 0; kt < 4; kt++) {
            const int kkb = kt * 16;
#pragma unroll
            for (int np = 0; np < 4; np++) {
                uint32_t bf0[2], bf1[2];
                ldsm_x4(bf0[0], bf0[1], bf1[0], bf1[1],
                        cK_u + (uint32_t)((np * 16 + b_noff + mrow) * PADA
                                          + kkb + b_koff) * 2u);
                mma_f16(s[2 * np],     qf[kt], bf0);
                mma_f16(s[2 * np + 1], qf[kt], bf1);
            }
        }
    };

    // prologue: stage loads for tiles 0,1; compute s(0)
    load_tile(0);
    load_tile(1);
    CP_WAIT(1);          // tile 0 complete
    __syncthreads();
    qk_tile(0);

    for (int i = 0; i < NTILE; i++) {
        CP_WAIT(0);      // tile i+1 complete (the only pending group)
        __syncthreads(); // visibility + all warps done with recycled stages
        if (i + 2 < NTILE) load_tile(i + 2);

        // ---- softmax on s (tile i) -> pa; s dies here ----
        float mx0 = -INFINITY, mx1 = -INFINITY;
#pragma unroll
        for (int nt = 0; nt < 8; nt++) {
            mx0 = fmaxf(mx0, fmaxf(s[nt][0], s[nt][1]));
            mx1 = fmaxf(mx1, fmaxf(s[nt][2], s[nt][3]));
        }
        mx0 = fmaxf(mx0, __shfl_xor_sync(0xffffffffu, mx0, 1));
        mx0 = fmaxf(mx0, __shfl_xor_sync(0xffffffffu, mx0, 2));
        mx1 = fmaxf(mx1, __shfl_xor_sync(0xffffffffu, mx1, 1));
        mx1 = fmaxf(mx1, __shfl_xor_sync(0xffffffffu, mx1, 2));

        // warp-uniform skip of rescale when the running max is unchanged
        if (__any_sync(0xffffffffu, (mx0 > m0) || (mx1 > m1))) {
            const float mn0 = fmaxf(m0, mx0);
            const float mn1 = fmaxf(m1, mx1);
            const float f0 = exp2f(m0 - mn0);
            const float f1 = exp2f(m1 - mn1);
            m0 = mn0; m1 = mn1;
#pragma unroll
            for (int nt = 0; nt < 9; nt++) {
                o[nt][0] *= f0; o[nt][1] *= f0;
                o[nt][2] *= f1; o[nt][3] *= f1;
            }
        }

        uint32_t pa[4][4];
#pragma unroll
        for (int kt = 0; kt < 4; kt++) {
            pa[kt][0] = h2_as_u32(h2exp2(__floats2half2_rn(s[2 * kt][0] - m0,
                                                           s[2 * kt][1] - m0)));
            pa[kt][1] = h2_as_u32(h2exp2(__floats2half2_rn(s[2 * kt][2] - m1,
                                                           s[2 * kt][3] - m1)));
            pa[kt][2] = h2_as_u32(h2exp2(__floats2half2_rn(s[2 * kt + 1][0] - m0,
                                                           s[2 * kt + 1][1] - m0)));
            pa[kt][3] = h2_as_u32(h2exp2(__floats2half2_rn(s[2 * kt + 1][2] - m1,
                                                           s[2 * kt + 1][3] - m1)));
        }

        // ---- PV(i): 9 n-groups (group 8 = ones row -> l) ----
        const uint32_t cV_u = sVt_u + (uint32_t)(i % 3) * TILE_HV * 2u;
#pragma unroll
        for (int kt = 0; kt < 4; kt++) {
            const int kkb = kt * 16;
#pragma unroll
            for (int np = 0; np < 4; np++) {
                uint32_t bf0[2], bf1[2];
                ldsm_x4(bf0[0], bf0[1], bf1[0], bf1[1],
                        cV_u + (uint32_t)((np * 16 + b_noff + mrow) * PADA
                                          + kkb + b_koff) * 2u);
                mma_f16(o[2 * np],     pa[kt], bf0);
                mma_f16(o[2 * np + 1], pa[kt], bf1);
            }
            {
                uint32_t bf[2];
                ldsm_x2(bf[0], bf[1],
                        cV_u + (uint32_t)((64 + mrow) * PADA + kkb + x2_koff) * 2u);
                mma_f16(o[8], pa[kt], bf);
            }
        }

        // ---- QK(i+1) into s (independent of this iteration's softmax) ----
        if (i + 1 < NTILE) qk_tile((i + 1) & 1);
    }

    // recover l from the quad leader (t=0 holds column 64)
    const float l0 = __shfl_sync(0xffffffffu, o[8][0], lane & 28);
    const float l1 = __shfl_sync(0xffffffffu, o[8][2], lane & 28);
    const float inv0 = 1.0f / l0;
    const float inv1 = 1.0f / l1;

    // epilogue: ctx half [B,S,D]
    const size_t row_lo = (size_t)b * S_ + q0 + wid * 16 + g;
#pragma unroll
    for (int nt = 0; nt < 8; nt++) {
        const int col = h * HD_ + nt * 8 + 2 * t;
        *reinterpret_cast<__half2*>(&ctx[row_lo * D_ + col]) =
            __floats2half2_rn(o[nt][0] * inv0, o[nt][1] * inv0);
        *reinterpret_cast<__half2*>(&ctx[(row_lo + 8) * D_ + col]) =
            __floats2half2_rn(o[nt][2] * inv1, o[nt][3] * inv1);
    }
}

// ---------------------------------------------------------------------------
extern "C" void kernel_launch(void* const* d_in, const int* in_sizes, int n_in,
                              void* d_out, int out_size) {
    const float* x  = (const float*)d_in[0];
    const float* Wq = (const float*)d_in[1];
    const float* bq = (const float*)d_in[2];
    const float* Wk = (const float*)d_in[3];
    const float* bk = (const float*)d_in[4];
    const float* Wv = (const float*)d_in[5];
    const float* bv = (const float*)d_in[6];
    const float* Wo = (const float*)d_in[7];
    const float* bo = (const float*)d_in[8];
    float* out = (float*)d_out;

    __half *xh, *q, *k, *v, *ctx, *wt;
    cudaGetSymbolAddress((void**)&xh,  g_xh);
    cudaGetSymbolAddress((void**)&q,   g_q);
    cudaGetSymbolAddress((void**)&k,   g_k);
    cudaGetSymbolAddress((void**)&v,   g_v);
    cudaGetSymbolAddress((void**)&ctx, g_ctx);
    cudaGetSymbolAddress((void**)&wt,  g_wt);
    __half* wto = wt + 3 * D_ * D_;

    const int gemm_smem = 4 * STAGE_H * 2;                  // 73728 B
    const int attn_smem = (2 * TILE_HK + 3 * TILE_HV) * 2;  // 49536 B
    cudaFuncSetAttribute(gemm_f16<0>, cudaFuncAttributeMaxDynamicSharedMemorySize, gemm_smem);
    cudaFuncSetAttribute(gemm_f16<3>, cudaFuncAttributeMaxDynamicSharedMemorySize, gemm_smem);
    cudaFuncSetAttribute(attn_f16, cudaFuncAttributeMaxDynamicSharedMemorySize, attn_smem);

    const int n4 = M_ * D_ / 4;
    f32_to_f16<<<(n4 + 255) / 256, 256>>>((const float4*)x, (__half2*)xh, n4);

    dim3 tr_grid(32, 32, 4), tr_blk(32, 8);
    transpose_w<<<tr_grid, tr_blk>>>(Wq, Wk, Wv, Wo, wt);

    // fused QKV GEMM: N = 3072
    dim3 gqkv(3 * D_ / 128, M_ / 128);   // (24, 32)
    gemm_f16<3><<<gqkv, 128, gemm_smem>>>(xh, wt, bq, bk, bv, q, k, v);

    dim3 attn_grid(S_ / 64, H_, B_);     // (32, 16, 2) = 1024 CTAs, 4/SM
    attn_f16<<<attn_grid, 128, attn_smem>>>(q, k, v, ctx);

    dim3 gg(D_ / 128, M_ / 128);         // (8, 32)
    gemm_f16<0><<<gg, 128, gemm_smem>>>(ctx, wto, bo, nullptr, nullptr, out, nullptr, nullptr);
}

// round 13
// speedup vs baseline: 1.0796x; 1.0150x over previous
#include <cuda_runtime.h>
#include <cuda_fp16.h>
#include <math.h>
#include <cstdint>

#define D_  1024
#define S_  2048
#define H_  16
#define HD_ 64
#define B_  2
#define M_  (B_ * S_)   // 4096

// Scratch (half precision activations/weights)
__device__ __half g_xh[M_ * D_];          // x in fp16
__device__ __half g_q[B_ * H_ * S_ * HD_]; // [B,H,S,HD], pre-scaled by 0.125*log2e
__device__ __half g_k[B_ * H_ * S_ * HD_]; // [B,H,S,HD]
__device__ __half g_v[B_ * H_ * HD_ * S_]; // [B,H,HD,S]  (transposed)
__device__ __half g_ctx[M_ * D_];          // [B,S,D]
__device__ __half g_wt[4][D_ * D_];        // transposed weights [N,K]: q,k,v,o

// ---------------------------------------------------------------------------
// helpers
// ---------------------------------------------------------------------------
__device__ __forceinline__ uint32_t smem_u32(const void* p) {
    uint32_t a;
    asm("{ .reg .u64 t; cvta.to.shared.u64 t, %1; cvt.u32.u64 %0, t; }"
        : "=r"(a) : "l"(p));
    return a;
}
__device__ __forceinline__ uint32_t h2_as_u32(__half2 h) {
    return *reinterpret_cast<uint32_t*>(&h);
}
__device__ __forceinline__ void cp_async16(uint32_t dst, const void* src) {
    asm volatile("cp.async.cg.shared.global [%0], [%1], 16;"
                 :: "r"(dst), "l"(src) : "memory");
}
#define CP_COMMIT() asm volatile("cp.async.commit_group;" ::: "memory")
#define CP_WAIT(n)  asm volatile("cp.async.wait_group %0;" :: "n"(n) : "memory")

// m16n8k16 fp16 MMA, fp32 accumulate
__device__ __forceinline__ void mma_f16(float* c, const uint32_t* a, const uint32_t* b) {
    asm volatile(
        "mma.sync.aligned.m16n8k16.row.col.f32.f16.f16.f32 "
        "{%0,%1,%2,%3}, {%4,%5,%6,%7}, {%8,%9}, {%0,%1,%2,%3};"
        : "+f"(c[0]), "+f"(c[1]), "+f"(c[2]), "+f"(c[3])
        : "r"(a[0]), "r"(a[1]), "r"(a[2]), "r"(a[3]), "r"(b[0]), "r"(b[1]));
}
__device__ __forceinline__ void ldsm_x4(uint32_t& r0, uint32_t& r1,
                                        uint32_t& r2, uint32_t& r3, uint32_t addr) {
    asm volatile("ldmatrix.sync.aligned.m8n8.x4.shared.b16 {%0,%1,%2,%3}, [%4];"
                 : "=r"(r0), "=r"(r1), "=r"(r2), "=r"(r3) : "r"(addr));
}
__device__ __forceinline__ void ldsm_x2(uint32_t& r0, uint32_t& r1, uint32_t addr) {
    asm volatile("ldmatrix.sync.aligned.m8n8.x2.shared.b16 {%0,%1}, [%2];"
                 : "=r"(r0), "=r"(r1) : "r"(addr));
}

// ---------------------------------------------------------------------------
// x: fp32 -> fp16
// ---------------------------------------------------------------------------
__global__ void f32_to_f16(const float4* __restrict__ in, __half2* __restrict__ out, int n4) {
    int i = blockIdx.x * blockDim.x + threadIdx.x;
    if (i < n4) {
        float4 v = in[i];
        out[2 * i]     = __floats2half2_rn(v.x, v.y);
        out[2 * i + 1] = __floats2half2_rn(v.z, v.w);
    }
}

// ---------------------------------------------------------------------------
// batched transpose + fp16: Wt[z][n][k] = half(W[z][k][n]), z in {0..3}
// ---------------------------------------------------------------------------
__global__ void transpose_w(const float* __restrict__ W0, const float* __restrict__ W1,
                            const float* __restrict__ W2, const float* __restrict__ W3,
                            __half* __restrict__ Wt) {
    __shared__ float tile[32][33];
    const float* W = (blockIdx.z == 0) ? W0 : (blockIdx.z == 1) ? W1
                     : (blockIdx.z == 2) ? W2 : W3;
    __half* dst = Wt + (size_t)blockIdx.z * D_ * D_;
    int x = blockIdx.x * 32 + threadIdx.x;
    int y = blockIdx.y * 32 + threadIdx.y;
#pragma unroll
    for (int j = 0; j < 32; j += 8)
        tile[threadIdx.y + j][threadIdx.x] = W[(size_t)(y + j) * D_ + x];
    __syncthreads();
    x = blockIdx.y * 32 + threadIdx.x;
    y = blockIdx.x * 32 + threadIdx.y;
#pragma unroll
    for (int j = 0; j < 32; j += 8)
        dst[(size_t)(y + j) * D_ + x] = __float2half(tile[threadIdx.x][threadIdx.y + j]);
}

// ---------------------------------------------------------------------------
// fp16 mma GEMM. CTA 128x128, 8 warps (warp tile 64x32), K-stage 64,
// cp.async double buffer, ldmatrix fragment loads, 2 CTAs/SM.
// MODE 0: fp32 row-major out (final projection), bias = b0, out = C0
// MODE 3: fused QKV — Wt is [3072,1024]; epilogue dispatches per 1024-col
//         segment: seg0 -> Q (C0, bias b0, * 0.125*log2e), seg1 -> K (C1, b1),
//         seg2 -> V (C2, b2, transposed [B,H,HD,S])
// ---------------------------------------------------------------------------
#define KS 64
#define NSTAGE (D_ / KS)          // 16
#define PADH 72                   // padded k-stride in halves (144B = 9*16B)
#define STAGE_H (128 * PADH)      // halves per buffer

#define QSCALE 0.18033688011112042f   // 0.125 * log2(e)

template <int MODE>
__global__ __launch_bounds__(256, 2) void gemm_f16(const __half* __restrict__ A,
                                                   const __half* __restrict__ Wt,
                                                   const float* __restrict__ b0,
                                                   const float* __restrict__ b1,
                                                   const float* __restrict__ b2,
                                                   void* __restrict__ C0,
                                                   void* __restrict__ C1,
                                                   void* __restrict__ C2) {
    extern __shared__ __half smh[];
    const int tid  = threadIdx.x;
    const int wid  = tid >> 5;             // 0..7
    const int lane = tid & 31;
    const int g = lane >> 2;
    const int t = lane & 3;
    const int warp_m = (wid & 1) * 64;     // 2 m-groups
    const int warp_n = (wid >> 1) * 32;    // 4 n-groups
    const int row0 = blockIdx.y * 128;
    const int col0 = blockIdx.x * 128;

    const uint32_t s_u = smem_u32(smh);

    // ldmatrix lane-address components
    const int mrow = lane & 7;
    const int msel = lane >> 3;            // matrix index 0..3
    const int a_roff = (msel & 1) * 8;     // A: m1,m3 are rows+8
    const int a_koff = (msel & 2) ? 8 : 0; // A: m2,m3 are k+8
    const int b_noff = (msel & 2) ? 8 : 0; // B: m2,m3 are n+8
    const int b_koff = (msel & 1) ? 8 : 0; // B: m1,m3 are k+8

    float acc[4][4][4];
#pragma unroll
    for (int mt = 0; mt < 4; mt++)
#pragma unroll
        for (int nt = 0; nt < 4; nt++)
#pragma unroll
            for (int r = 0; r < 4; r++) acc[mt][nt][r] = 0.0f;

    auto issue_stage = [&](int s) {
        const int k0 = s * KS;
        const int buf = s & 1;
        const uint32_t baseA = s_u + (uint32_t)buf * STAGE_H * 2u;
        const uint32_t baseB = s_u + (uint32_t)(2 + buf) * STAGE_H * 2u;
#pragma unroll
        for (int i = 0; i < 4; i++) {
            const int lin = tid + i * 256;   // 0..1023
            const int row = lin >> 3;
            const int f8  = (lin & 7) * 8;
            cp_async16(baseA + (uint32_t)(row * PADH + f8) * 2u,
                       &A[(size_t)(row0 + row) * D_ + k0 + f8]);
            cp_async16(baseB + (uint32_t)(row * PADH + f8) * 2u,
                       &Wt[(size_t)(col0 + row) * D_ + k0 + f8]);
        }
        CP_COMMIT();
    };

    issue_stage(0);
    issue_stage(1);

    for (int s = 0; s < NSTAGE; s++) {
        if (s + 1 < NSTAGE) { CP_WAIT(1); } else { CP_WAIT(0); }
        __syncthreads();

        const int buf = s & 1;
        const uint32_t pA_u = s_u + (uint32_t)buf * STAGE_H * 2u;
        const uint32_t pB_u = s_u + (uint32_t)(2 + buf) * STAGE_H * 2u;

#pragma unroll
        for (int k16 = 0; k16 < 4; k16++) {
            const int kkb = k16 * 16;
            uint32_t af[4][4], bf[4][2];
#pragma unroll
            for (int mt = 0; mt < 4; mt++) {
                ldsm_x4(af[mt][0], af[mt][1], af[mt][2], af[mt][3],
                        pA_u + (uint32_t)((warp_m + mt * 16 + a_roff + mrow) * PADH
                                          + kkb + a_koff) * 2u);
            }
#pragma unroll
            for (int np = 0; np < 2; np++) {
                ldsm_x4(bf[2 * np][0], bf[2 * np][1], bf[2 * np + 1][0], bf[2 * np + 1][1],
                        pB_u + (uint32_t)((warp_n + np * 16 + b_noff + mrow) * PADH
                                          + kkb + b_koff) * 2u);
            }
#pragma unroll
            for (int mt = 0; mt < 4; mt++)
#pragma unroll
                for (int nt = 0; nt < 4; nt++)
                    mma_f16(acc[mt][nt], af[mt], bf[nt]);
        }
        __syncthreads();
        if (s + 2 < NSTAGE) issue_stage(s + 2);
    }

    // epilogue
#pragma unroll
    for (int mt = 0; mt < 4; mt++) {
        const int r_lo = row0 + warp_m + mt * 16 + g;
#pragma unroll
        for (int nt = 0; nt < 4; nt++) {
            const int cc = col0 + warp_n + nt * 8 + 2 * t;
            const int seg = cc >> 10;          // 0=Q 1=K 2=V (MODE 3; CTA-uniform)
            const int lc  = cc & (D_ - 1);
            const float* bias = (MODE == 0) ? b0
                               : (seg == 0) ? b0 : (seg == 1) ? b1 : b2;
            const int bidx = (MODE == 0) ? cc : lc;
            const float bx = bias[bidx];
            const float by = bias[bidx + 1];
#pragma unroll
            for (int half_ = 0; half_ < 2; half_++) {
                const int rr = r_lo + half_ * 8;
                const float v0 = acc[mt][nt][2 * half_ + 0] + bx;
                const float v1 = acc[mt][nt][2 * half_ + 1] + by;
                if (MODE == 0) {
                    float* C = (float*)C0;
                    *reinterpret_cast<float2*>(&C[(size_t)rr * D_ + cc]) =
                        make_float2(v0, v1);
                } else {
                    const int bb = rr >> 11;
                    const int ss = rr & (S_ - 1);
                    const int hh = lc >> 6;
                    const int dd = lc & (HD_ - 1);
                    if (seg == 0) {
                        __half* C = (__half*)C0;
                        *reinterpret_cast<__half2*>(
                            &C[(((size_t)(bb * H_ + hh)) * S_ + ss) * HD_ + dd]) =
                            __floats2half2_rn(v0 * QSCALE, v1 * QSCALE);
                    } else if (seg == 1) {
                        __half* C = (__half*)C1;
                        *reinterpret_cast<__half2*>(
                            &C[(((size_t)(bb * H_ + hh)) * S_ + ss) * HD_ + dd]) =
                            __floats2half2_rn(v0, v1);
                    } else {
                        __half* C = (__half*)C2;
                        C[(((size_t)(bb * H_ + hh)) * HD_ + dd) * S_ + ss] = __float2half(v0);
                        C[(((size_t)(bb * H_ + hh)) * HD_ + dd + 1) * S_ + ss] = __float2half(v1);
                    }
                }
            }
        }
    }
}

// ---------------------------------------------------------------------------
// fp16 tensor-core flash attention, 64-query tile, 4 warps, 4 CTAs/SM.
// log2-domain softmax, cross-iteration software pipeline (softmax(i) uses
// scores computed in iteration i-1). K ring 2-stage, V ring 3-stage,
// ONE __syncthreads per iteration.  (unchanged from Round 12)
// ---------------------------------------------------------------------------
#define PADA 72
#define TILE_HK (64 * PADA)   // halves per K tile
#define TILE_HV (72 * PADA)   // halves per V tile (64 data rows + 8 ones/zeros)
#define NTILE (S_ / 64)       // 32

__global__ __launch_bounds__(128, 4) void attn_f16(const __half* __restrict__ Q,
                                                   const __half* __restrict__ K,
                                                   const __half* __restrict__ V,
                                                   __half* __restrict__ ctx) {
    extern __shared__ __half sah[];
    const int tid  = threadIdx.x;
    const int wid  = tid >> 5;        // 0..3
    const int lane = tid & 31;
    const int g = lane >> 2;
    const int t = lane & 3;
    const int qt = blockIdx.x;
    const int h  = blockIdx.y;
    const int b  = blockIdx.z;
    const size_t bh = ((size_t)b * H_ + h);
    const int q0 = qt * 64;

    __half* sK  = sah;
    __half* sVt = sah + 2 * TILE_HK;
    const uint32_t sK_u  = smem_u32(sK);
    const uint32_t sVt_u = smem_u32(sVt);

    const int mrow = lane & 7;
    const int msel = lane >> 3;
    const int b_noff = (msel & 2) ? 8 : 0;
    const int b_koff = (msel & 1) ? 8 : 0;
    const int x2_koff = (lane & 8) ? 8 : 0;

    for (int idx = tid; idx < 3 * 8 * PADA; idx += 128) {
        const int buf = idx / (8 * PADA);
        const int rem = idx % (8 * PADA);
        const int r = 64 + rem / PADA;
        const int c = rem % PADA;
        sVt[buf * TILE_HV + r * PADA + c] = __float2half(r == 64 ? 1.0f : 0.0f);
    }

    const __half* Qp = Q + (bh * S_ + q0 + wid * 16) * HD_;
    uint32_t qf[4][4];
#pragma unroll
    for (int kt = 0; kt < 4; kt++) {
        const int kk = kt * 16 + 2 * t;
        qf[kt][0] = *reinterpret_cast<const uint32_t*>(&Qp[g * HD_ + kk]);
        qf[kt][1] = *reinterpret_cast<const uint32_t*>(&Qp[(g + 8) * HD_ + kk]);
        qf[kt][2] = *reinterpret_cast<const uint32_t*>(&Qp[g * HD_ + kk + 8]);
        qf[kt][3] = *reinterpret_cast<const uint32_t*>(&Qp[(g + 8) * HD_ + kk + 8]);
    }

    float o[9][4];
#pragma unroll
    for (int nt = 0; nt < 9; nt++)
#pragma unroll
        for (int r = 0; r < 4; r++) o[nt][r] = 0.0f;
    float m0 = -INFINITY, m1 = -INFINITY;

    const __half* Kbase = K + bh * S_ * HD_;
    const __half* Vbase = V + bh * (size_t)HD_ * S_;

    auto load_tile = [&](int i) {
        const __half* Kp = Kbase + (size_t)i * 64 * HD_;
        const uint32_t dK = sK_u + (uint32_t)(i & 1) * TILE_HK * 2u;
        const uint32_t dV = sVt_u + (uint32_t)(i % 3) * TILE_HV * 2u;
#pragma unroll
        for (int j = 0; j < 4; j++) {
            const int lin = tid + j * 128;
            const int row = lin >> 3;
            const int f8  = (lin & 7) * 8;
            cp_async16(dK + (uint32_t)(row * PADA + f8) * 2u, Kp + row * HD_ + f8);
            cp_async16(dV + (uint32_t)(row * PADA + f8) * 2u,
                       Vbase + (size_t)row * S_ + i * 64 + f8);
        }
        CP_COMMIT();
    };

    float s[8][4];

    auto qk_tile = [&](int stage) {
        const uint32_t cK_u = sK_u + (uint32_t)stage * TILE_HK * 2u;
#pragma unroll
        for (int nt = 0; nt < 8; nt++)
#pragma unroll
            for (int r = 0; r < 4; r++) s[nt][r] = 0.0f;
#pragma unroll
        for (int kt = 0; kt < 4; kt++) {
            const int kkb = kt * 16;
#pragma unroll
            for (int np = 0; np < 4; np++) {
                uint32_t bf0[2], bf1[2];
                ldsm_x4(bf0[0], bf0[1], bf1[0], bf1[1],
                        cK_u + (uint32_t)((np * 16 + b_noff + mrow) * PADA
                                          + kkb + b_koff) * 2u);
                mma_f16(s[2 * np],     qf[kt], bf0);
                mma_f16(s[2 * np + 1], qf[kt], bf1);
            }
        }
    };

    load_tile(0);
    load_tile(1);
    CP_WAIT(1);
    __syncthreads();
    qk_tile(0);

    for (int i = 0; i < NTILE; i++) {
        CP_WAIT(0);
        __syncthreads();
        if (i + 2 < NTILE) load_tile(i + 2);

        float mx0 = -INFINITY, mx1 = -INFINITY;
#pragma unroll
        for (int nt = 0; nt < 8; nt++) {
            mx0 = fmaxf(mx0, fmaxf(s[nt][0], s[nt][1]));
            mx1 = fmaxf(mx1, fmaxf(s[nt][2], s[nt][3]));
        }
        mx0 = fmaxf(mx0, __shfl_xor_sync(0xffffffffu, mx0, 1));
        mx0 = fmaxf(mx0, __shfl_xor_sync(0xffffffffu, mx0, 2));
        mx1 = fmaxf(mx1, __shfl_xor_sync(0xffffffffu, mx1, 1));
        mx1 = fmaxf(mx1, __shfl_xor_sync(0xffffffffu, mx1, 2));

        if (__any_sync(0xffffffffu, (mx0 > m0) || (mx1 > m1))) {
            const float mn0 = fmaxf(m0, mx0);
            const float mn1 = fmaxf(m1, mx1);
            const float f0 = exp2f(m0 - mn0);
            const float f1 = exp2f(m1 - mn1);
            m0 = mn0; m1 = mn1;
#pragma unroll
            for (int nt = 0; nt < 9; nt++) {
                o[nt][0] *= f0; o[nt][1] *= f0;
                o[nt][2] *= f1; o[nt][3] *= f1;
            }
        }

        uint32_t pa[4][4];
#pragma unroll
        for (int kt = 0; kt < 4; kt++) {
            pa[kt][0] = h2_as_u32(h2exp2(__floats2half2_rn(s[2 * kt][0] - m0,
                                                           s[2 * kt][1] - m0)));
            pa[kt][1] = h2_as_u32(h2exp2(__floats2half2_rn(s[2 * kt][2] - m1,
                                                           s[2 * kt][3] - m1)));
            pa[kt][2] = h2_as_u32(h2exp2(__floats2half2_rn(s[2 * kt + 1][0] - m0,
                                                           s[2 * kt + 1][1] - m0)));
            pa[kt][3] = h2_as_u32(h2exp2(__floats2half2_rn(s[2 * kt + 1][2] - m1,
                                                           s[2 * kt + 1][3] - m1)));
        }

        const uint32_t cV_u = sVt_u + (uint32_t)(i % 3) * TILE_HV * 2u;
#pragma unroll
        for (int kt = 0; kt < 4; kt++) {
            const int kkb = kt * 16;
#pragma unroll
            for (int np = 0; np < 4; np++) {
                uint32_t bf0[2], bf1[2];
                ldsm_x4(bf0[0], bf0[1], bf1[0], bf1[1],
                        cV_u + (uint32_t)((np * 16 + b_noff + mrow) * PADA
                                          + kkb + b_koff) * 2u);
                mma_f16(o[2 * np],     pa[kt], bf0);
                mma_f16(o[2 * np + 1], pa[kt], bf1);
            }
            {
                uint32_t bf[2];
                ldsm_x2(bf[0], bf[1],
                        cV_u + (uint32_t)((64 + mrow) * PADA + kkb + x2_koff) * 2u);
                mma_f16(o[8], pa[kt], bf);
            }
        }

        if (i + 1 < NTILE) qk_tile((i + 1) & 1);
    }

    const float l0 = __shfl_sync(0xffffffffu, o[8][0], lane & 28);
    const float l1 = __shfl_sync(0xffffffffu, o[8][2], lane & 28);
    const float inv0 = 1.0f / l0;
    const float inv1 = 1.0f / l1;

    const size_t row_lo = (size_t)b * S_ + q0 + wid * 16 + g;
#pragma unroll
    for (int nt = 0; nt < 8; nt++) {
        const int col = h * HD_ + nt * 8 + 2 * t;
        *reinterpret_cast<__half2*>(&ctx[row_lo * D_ + col]) =
            __floats2half2_rn(o[nt][0] * inv0, o[nt][1] * inv0);
        *reinterpret_cast<__half2*>(&ctx[(row_lo + 8) * D_ + col]) =
            __floats2half2_rn(o[nt][2] * inv1, o[nt][3] * inv1);
    }
}

// ---------------------------------------------------------------------------
extern "C" void kernel_launch(void* const* d_in, const int* in_sizes, int n_in,
                              void* d_out, int out_size) {
    const float* x  = (const float*)d_in[0];
    const float* Wq = (const float*)d_in[1];
    const float* bq = (const float*)d_in[2];
    const float* Wk = (const float*)d_in[3];
    const float* bk = (const float*)d_in[4];
    const float* Wv = (const float*)d_in[5];
    const float* bv = (const float*)d_in[6];
    const float* Wo = (const float*)d_in[7];
    const float* bo = (const float*)d_in[8];
    float* out = (float*)d_out;

    __half *xh, *q, *k, *v, *ctx, *wt;
    cudaGetSymbolAddress((void**)&xh,  g_xh);
    cudaGetSymbolAddress((void**)&q,   g_q);
    cudaGetSymbolAddress((void**)&k,   g_k);
    cudaGetSymbolAddress((void**)&v,   g_v);
    cudaGetSymbolAddress((void**)&ctx, g_ctx);
    cudaGetSymbolAddress((void**)&wt,  g_wt);
    __half* wto = wt + 3 * D_ * D_;

    const int gemm_smem = 4 * STAGE_H * 2;                  // 73728 B
    const int attn_smem = (2 * TILE_HK + 3 * TILE_HV) * 2;  // 49536 B
    cudaFuncSetAttribute(gemm_f16<0>, cudaFuncAttributeMaxDynamicSharedMemorySize, gemm_smem);
    cudaFuncSetAttribute(gemm_f16<3>, cudaFuncAttributeMaxDynamicSharedMemorySize, gemm_smem);
    cudaFuncSetAttribute(attn_f16, cudaFuncAttributeMaxDynamicSharedMemorySize, attn_smem);

    const int n4 = M_ * D_ / 4;
    f32_to_f16<<<(n4 + 255) / 256, 256>>>((const float4*)x, (__half2*)xh, n4);

    dim3 tr_grid(32, 32, 4), tr_blk(32, 8);
    transpose_w<<<tr_grid, tr_blk>>>(Wq, Wk, Wv, Wo, wt);

    // fused QKV GEMM: N = 3072
    dim3 gqkv(3 * D_ / 128, M_ / 128);   // (24, 32)
    gemm_f16<3><<<gqkv, 256, gemm_smem>>>(xh, wt, bq, bk, bv, q, k, v);

    dim3 attn_grid(S_ / 64, H_, B_);     // (32, 16, 2) = 1024 CTAs, 4/SM
    attn_f16<<<attn_grid, 128, attn_smem>>>(q, k, v, ctx);

    dim3 gg(D_ / 128, M_ / 128);         // (8, 32)
    gemm_f16<0><<<gg, 256, gemm_smem>>>(ctx, wto, bo, nullptr, nullptr, out, nullptr, nullptr);
}